// round 1
// baseline (speedup 1.0000x reference)
#include <cuda_runtime.h>
#include <cstdint>
#include <math.h>

// Problem dims
#define NE     16384     // codebook entries
#define CD     256       // embedding dim
#define HW     1024      // 32*32 tokens per batch image
#define NTOK   4096      // 4 * 1024
#define ZQ_N   (NTOK * CD)   // 1048576 output elements for z_q
#define NCUTS  32
#define EMB    512
#define BATCH  4

// VQ kernel tiling
#define TPB      256
#define TOK_BLK  32      // tokens per block
#define NCHUNK   256     // codes per N-chunk
#define KS_SZ    32      // K-slice size
#define BROW     36      // padded floats per code row in smem (32 k + 4 pad)
#define XROW     260     // padded floats per token row (256 + 4 pad)

#define XS_FLOATS (TOK_BLK * XROW)            // 8320
#define BS_FLOATS (2 * NCHUNK * BROW)         // 18432 (double buffered)
#define SMEM_BYTES ((XS_FLOATS + BS_FLOATS) * 4 + TOK_BLK * 4)

// scratch for 0.5*||e||^2 (device global: no allocations allowed)
__device__ float g_halfnorm[NE];

// ---------------- cp.async helpers ----------------
__device__ __forceinline__ void cp_async16(float* sdst, const float* gsrc) {
    unsigned sa = (unsigned)__cvta_generic_to_shared(sdst);
    asm volatile("cp.async.cg.shared.global [%0], [%1], 16;\n" :: "r"(sa), "l"(gsrc));
}
__device__ __forceinline__ void cp_commit() {
    asm volatile("cp.async.commit_group;\n");
}
template <int N>
__device__ __forceinline__ void cp_wait() {
    asm volatile("cp.async.wait_group %0;\n" :: "n"(N));
}

// ---------------- half-norm precompute ----------------
__global__ void halfnorm_kernel(const float* __restrict__ cb) {
    int gw   = (blockIdx.x * blockDim.x + threadIdx.x) >> 5;
    int lane = threadIdx.x & 31;
    if (gw >= NE) return;
    const float4* row = reinterpret_cast<const float4*>(cb + (size_t)gw * CD);
    float s = 0.f;
    #pragma unroll
    for (int i = 0; i < 2; i++) {
        float4 v = row[lane + 32 * i];
        s += v.x * v.x + v.y * v.y + v.z * v.z + v.w * v.w;
    }
    #pragma unroll
    for (int o = 16; o; o >>= 1) s += __shfl_xor_sync(0xffffffffu, s, o);
    if (lane == 0) g_halfnorm[gw] = 0.5f * s;
}

// ---------------- slice loader: codes[n0..n0+255][ks*32..+31] -> smem ----------------
__device__ __forceinline__ void load_slice(float* bdst, const float* __restrict__ cb,
                                           int n0, int ks, int tid) {
    const int g = tid & 7;     // 16B group within the 32-float k-slice
    const int r = tid >> 3;    // row 0..31, strided by 32 below
    const float* src = cb + (size_t)(n0 + r) * CD + ks * KS_SZ + g * 4;
    float* dst = bdst + r * BROW + g * 4;
    #pragma unroll
    for (int it = 0; it < 8; it++)
        cp_async16(dst + it * 32 * BROW, src + it * 32 * CD);
}

// ---------------- fused VQ: GEMM + argmax(x.e - 0.5||e||^2) + gather ----------------
__global__ void __launch_bounds__(TPB, 1)
vq_kernel(const float* __restrict__ z, const float* __restrict__ cb,
          float* __restrict__ out) {
    extern __shared__ float smem[];
    float* xs = smem;                       // [32][260] token-major
    float* bs = smem + XS_FLOATS;           // [2][256][36] code rows (padded)
    int* idx_sm = (int*)(bs + BS_FLOATS);   // [32] winning indices

    const int tid  = threadIdx.x;
    const int lane = tid & 31;
    const int warp = tid >> 5;              // 8 warps: m-group; lane = n-group

    const int t0 = blockIdx.x * TOK_BLK;    // first token of this block
    const int bb = t0 >> 10;                // batch index (32 | 1024, so uniform)
    const int p0 = t0 & 1023;               // position within image

    // ---- load x tile [32 tok][256 c], coalesced on gmem ----
    const float* zb = z + (size_t)bb * CD * HW + p0;
    #pragma unroll 4
    for (int i = 0; i < 32; i++) {
        int c = warp + 8 * i;
        xs[lane * XROW + c] = zb[(size_t)c * HW + lane];
    }

    float best[4];
    int   bidx[4];
    #pragma unroll
    for (int i = 0; i < 4; i++) { best[i] = -INFINITY; bidx[i] = 0; }

    int buf = 0;
    load_slice(bs, cb, 0, 0, tid);
    cp_commit();

    const float* xbase = xs + warp * 4 * XROW;

    for (int chunk = 0; chunk < NE / NCHUNK; chunk++) {
        const int n0 = chunk * NCHUNK;
        float acc[4][8];
        #pragma unroll
        for (int i = 0; i < 4; i++)
            #pragma unroll
            for (int j = 0; j < 8; j++) acc[i][j] = 0.f;

        for (int ks = 0; ks < 8; ks++) {
            // prefetch next slice into the other buffer
            int nks = ks + 1, nn0 = n0;
            if (nks == 8) { nks = 0; nn0 += NCHUNK; }
            if (nn0 < NE) {
                load_slice(bs + (buf ^ 1) * NCHUNK * BROW, cb, nn0, nks, tid);
                cp_commit();
                cp_wait<1>();
            } else {
                cp_wait<0>();
            }
            __syncthreads();

            const float* bthr = bs + buf * NCHUNK * BROW + lane * BROW; // code n = n0 + lane + 32*j
            const float* xk   = xbase + ks * KS_SZ;

            #pragma unroll 2
            for (int k4 = 0; k4 < 8; k4++) {
                float4 a[4], b[8];
                #pragma unroll
                for (int i = 0; i < 4; i++)
                    a[i] = *(const float4*)(xk + i * XROW + k4 * 4);   // broadcast (same addr per warp)
                #pragma unroll
                for (int j = 0; j < 8; j++)
                    b[j] = *(const float4*)(bthr + j * 32 * BROW + k4 * 4); // conflict-free (36-fl rows)
                #pragma unroll
                for (int i = 0; i < 4; i++)
                    #pragma unroll
                    for (int j = 0; j < 8; j++) {
                        acc[i][j] = fmaf(a[i].x, b[j].x, acc[i][j]);
                        acc[i][j] = fmaf(a[i].y, b[j].y, acc[i][j]);
                        acc[i][j] = fmaf(a[i].z, b[j].z, acc[i][j]);
                        acc[i][j] = fmaf(a[i].w, b[j].w, acc[i][j]);
                    }
            }
            __syncthreads();
            buf ^= 1;
        }

        // epilogue: fold chunk into running best (score = dot - 0.5||e||^2, argmax)
        #pragma unroll
        for (int j = 0; j < 8; j++) {
            int n = n0 + lane + 32 * j;
            float hn = __ldg(&g_halfnorm[n]);
            #pragma unroll
            for (int i = 0; i < 4; i++) {
                float s = acc[i][j] - hn;
                if (s > best[i]) { best[i] = s; bidx[i] = n; }  // strict >: first (lowest n) wins ties
            }
        }
    }

    // cross-lane reduce within warp (all lanes share the same 4 tokens)
    #pragma unroll
    for (int i = 0; i < 4; i++) {
        float sc = best[i];
        int bi = bidx[i];
        #pragma unroll
        for (int o = 16; o; o >>= 1) {
            float sc2 = __shfl_xor_sync(0xffffffffu, sc, o);
            int   bi2 = __shfl_xor_sync(0xffffffffu, bi, o);
            if (sc2 > sc || (sc2 == sc && bi2 < bi)) { sc = sc2; bi = bi2; }
        }
        if (lane == 0) idx_sm[warp * 4 + i] = bi;
    }
    __syncthreads();

    // gather codebook rows -> z_q in [B,C,H,W] layout (coalesced stores)
    const int myidx = idx_sm[lane];
    float* ob = out + (size_t)bb * CD * HW + p0 + lane;
    const float* crow = cb + (size_t)myidx * CD;
    #pragma unroll 4
    for (int i = 0; i < 32; i++) {
        int c = warp + 8 * i;
        ob[(size_t)c * HW] = crow[c];
    }
}

// ---------------- spherical distance loss ----------------
__global__ void sph_kernel(const float* __restrict__ ie, const float* __restrict__ pr,
                           float* __restrict__ out) {
    int e = blockIdx.x * blockDim.x + threadIdx.x;
    if (e >= EMB) return;

    float p[BATCH];
    float pn = 0.f;
    #pragma unroll
    for (int b = 0; b < BATCH; b++) { p[b] = pr[b * EMB + e]; pn += p[b] * p[b]; }
    pn = fmaxf(sqrtf(pn), 1e-12f);
    #pragma unroll
    for (int b = 0; b < BATCH; b++) p[b] /= pn;

    float acc = 0.f;
    for (int j = 0; j < NCUTS; j++) {
        float q[BATCH];
        float qn = 0.f;
        #pragma unroll
        for (int b = 0; b < BATCH; b++) {
            q[b] = ie[(size_t)(j * BATCH + b) * EMB + e];
            qn += q[b] * q[b];
        }
        qn = fmaxf(sqrtf(qn), 1e-12f);
        float d2 = 0.f;
        #pragma unroll
        for (int b = 0; b < BATCH; b++) {
            float df = q[b] / qn - p[b];
            d2 += df * df;
        }
        float h = fminf(0.5f * sqrtf(d2), 1.0f);
        float a = asinf(h);
        acc += 2.0f * a * a;
    }
    out[e] = acc * (1.0f / NCUTS);
}

// ---------------- launch ----------------
extern "C" void kernel_launch(void* const* d_in, const int* in_sizes, int n_in,
                              void* d_out, int out_size) {
    const float* z  = (const float*)d_in[0];   // [4,256,32,32]
    const float* cb = (const float*)d_in[1];   // [16384,256]
    const float* ie = (const float*)d_in[2];   // [32,4,512]
    const float* pr = (const float*)d_in[3];   // [4,512]
    float* out = (float*)d_out;                // z_q (1048576) then dists (512)

    cudaFuncSetAttribute(vq_kernel, cudaFuncAttributeMaxDynamicSharedMemorySize, SMEM_BYTES);

    halfnorm_kernel<<<NE / 8, 256>>>(cb);
    vq_kernel<<<NTOK / TOK_BLK, TPB, SMEM_BYTES>>>(z, cb, out);
    if (out_size >= ZQ_N + EMB)
        sph_kernel<<<(EMB + 255) / 256, 256>>>(ie, pr, out + ZQ_N);
}

// round 3
// speedup vs baseline: 4.9395x; 4.9395x over previous
#include <cuda_runtime.h>
#include <cuda_bf16.h>
#include <cstdint>
#include <math.h>

typedef unsigned long long ull;

// ---------------- problem dims ----------------
#define NE     16384
#define CD     256
#define HW     1024
#define NTOK   4096
#define ZQ_N   (NTOK * CD)
#define NCUTS  32
#define EMB    512
#define BATCH  4

// ---------------- GEMM tiling ----------------
// CTA tile: 128 tokens x 128 codes, K=256 streamed in 8 slices of 32.
#define KS      32
#define NSLICE  8
#define ROWB    80                  // smem bytes/row: 64 data + 16 pad (conflict-free ldmatrix)
#define PLANE_B (128 * ROWB)        // 10240
#define STAGE_B (2 * PLANE_B)       // A plane + B plane = 20480
#define SMEM_B  (2 * STAGE_B)       // double buffered = 40960

// ---------------- device globals ----------------
__device__ __align__(16) __nv_bfloat16 g_Ah[NTOK * CD];      // z, bf16, token-major
__device__ __align__(16) __nv_bfloat16 g_Bh[NE * CD];        // codebook, bf16
__device__ float g_hn[NE];                                   // 0.5*||e||^2 exact fp32
__device__ ull   g_top[(size_t)NTOK * 512];                  // top-2 per (ntile, n-half)
__device__ int   g_best[NTOK];

// ---------------- asm helpers ----------------
static __device__ __forceinline__ uint32_t smem_u32(const void* p) {
    uint32_t a;
    asm("{ .reg .u64 t; cvta.to.shared.u64 t, %1; cvt.u32.u64 %0, t; }" : "=r"(a) : "l"(p));
    return a;
}
static __device__ __forceinline__ void cp16(uint32_t dst, const void* src) {
    asm volatile("cp.async.cg.shared.global [%0], [%1], 16;" :: "r"(dst), "l"(src));
}
static __device__ __forceinline__ void cp_commit() {
    asm volatile("cp.async.commit_group;");
}
template <int N> static __device__ __forceinline__ void cp_wait() {
    asm volatile("cp.async.wait_group %0;" :: "n"(N));
}
#define LDSM4(r, addr) \
    asm volatile("ldmatrix.sync.aligned.m8n8.x4.shared.b16 {%0,%1,%2,%3}, [%4];" \
        : "=r"((r)[0]), "=r"((r)[1]), "=r"((r)[2]), "=r"((r)[3]) : "r"(addr))
#define MMA16816(d, a, b0, b1) \
    asm volatile("mma.sync.aligned.m16n8k16.row.col.f32.bf16.bf16.f32 " \
        "{%0,%1,%2,%3},{%4,%5,%6,%7},{%8,%9},{%0,%1,%2,%3};" \
        : "+f"((d)[0]), "+f"((d)[1]), "+f"((d)[2]), "+f"((d)[3]) \
        : "r"((a)[0]), "r"((a)[1]), "r"((a)[2]), "r"((a)[3]), "r"(b0), "r"(b1))

static __device__ __forceinline__ uint32_t mono_f32(float f) {
    uint32_t b = __float_as_uint(f);
    return (b & 0x80000000u) ? ~b : (b | 0x80000000u);
}
static __device__ __forceinline__ ull umax64(ull a, ull b) { return a > b ? a : b; }
static __device__ __forceinline__ ull umin64(ull a, ull b) { return a < b ? a : b; }

// ================= prep kernels =================
__global__ void convA_kernel(const float* __restrict__ z) {
    int t = blockIdx.x * 256 + threadIdx.x;           // 4096*32 threads
    int token = t >> 5, c8 = t & 31;
    int bb = token >> 10, p = token & 1023;
    __align__(16) __nv_bfloat16 h[8];
    #pragma unroll
    for (int i = 0; i < 8; i++)
        h[i] = __float2bfloat16(z[((size_t)bb * CD + c8 * 8 + i) * HW + p]);
    *(uint4*)&g_Ah[(size_t)token * CD + c8 * 8] = *(const uint4*)h;
}

__global__ void convB_kernel(const float* __restrict__ cb) {
    int t = blockIdx.x * 256 + threadIdx.x;           // 16384*32 threads
    int n = t >> 5, c8 = t & 31;
    __align__(16) __nv_bfloat16 h[8];
    #pragma unroll
    for (int i = 0; i < 8; i++)
        h[i] = __float2bfloat16(cb[(size_t)n * CD + c8 * 8 + i]);
    *(uint4*)&g_Bh[(size_t)n * CD + c8 * 8] = *(const uint4*)h;
}

__global__ void halfnorm_kernel(const float* __restrict__ cb) {
    int gw = (blockIdx.x * blockDim.x + threadIdx.x) >> 5;
    int lane = threadIdx.x & 31;
    if (gw >= NE) return;
    const float4* row = reinterpret_cast<const float4*>(cb + (size_t)gw * CD);
    float s = 0.f;
    #pragma unroll
    for (int i = 0; i < 2; i++) {
        float4 v = row[lane + 32 * i];
        s += v.x * v.x + v.y * v.y + v.z * v.z + v.w * v.w;
    }
    #pragma unroll
    for (int o = 16; o; o >>= 1) s += __shfl_xor_sync(0xffffffffu, s, o);
    if (lane == 0) g_hn[gw] = 0.5f * s;
}

// ================= tensor-core VQ GEMM (nomination pass) =================
__global__ void __launch_bounds__(256) vq_gemm() {
    extern __shared__ unsigned char smem[];
    const uint32_t sb = smem_u32(smem);
    const int tid = threadIdx.x;
    const int lane = tid & 31;
    const int wid = tid >> 5;            // 8 warps: wm = wid>>1 (4), wn = wid&1 (2)
    const int wm = wid >> 1, wn = wid & 1;
    const int ntile = blockIdx.x;        // 128
    const int mtile = blockIdx.y;        // 32

    const __nv_bfloat16* Abase = g_Ah + (size_t)mtile * 128 * CD;
    const __nv_bfloat16* Bbase = g_Bh + (size_t)ntile * 128 * CD;

    // loader: 128 threads -> A rows, 128 threads -> B rows; 64B (one slice-row) each
    const int lrow = tid & 127;
    const char* lsrc = (const char*)((tid < 128 ? Abase : Bbase) + (size_t)lrow * CD);
    const uint32_t ldst = sb + (tid < 128 ? 0 : PLANE_B) + lrow * ROWB;

    // prologue: stage slices 0,1
    #pragma unroll
    for (int s = 0; s < 2; s++) {
        #pragma unroll
        for (int g = 0; g < 4; g++)
            cp16(ldst + s * STAGE_B + g * 16, lsrc + s * 64 + g * 16);
        cp_commit();
    }

    float acc[2][8][4];
    #pragma unroll
    for (int mi = 0; mi < 2; mi++)
        #pragma unroll
        for (int ni = 0; ni < 8; ni++)
            #pragma unroll
            for (int c = 0; c < 4; c++) acc[mi][ni][c] = 0.f;

    const uint32_t arow = (wm * 32 + (lane & 15)) * ROWB + (lane >> 4) * 16;
    const uint32_t brow = (wn * 64 + (lane & 15)) * ROWB + (lane >> 4) * 16;

    for (int ks = 0; ks < NSLICE; ks++) {
        const int s = ks & 1;
        if (ks < NSLICE - 1) cp_wait<1>(); else cp_wait<0>();
        __syncthreads();

        const uint32_t ab = sb + s * STAGE_B;
        const uint32_t bbp = ab + PLANE_B;
        #pragma unroll
        for (int kk = 0; kk < 2; kk++) {
            uint32_t a[2][4], b[4][4];
            #pragma unroll
            for (int mi = 0; mi < 2; mi++)
                LDSM4(a[mi], ab + arow + mi * 16 * ROWB + kk * 32);
            #pragma unroll
            for (int nf = 0; nf < 4; nf++)
                LDSM4(b[nf], bbp + brow + nf * 16 * ROWB + kk * 32);
            #pragma unroll
            for (int mi = 0; mi < 2; mi++)
                #pragma unroll
                for (int nf = 0; nf < 4; nf++) {
                    MMA16816(acc[mi][nf * 2 + 0], a[mi], b[nf][0], b[nf][2]);
                    MMA16816(acc[mi][nf * 2 + 1], a[mi], b[nf][1], b[nf][3]);
                }
        }
        __syncthreads();
        if (ks + 2 < NSLICE) {
            #pragma unroll
            for (int g = 0; g < 4; g++)
                cp16(ldst + s * STAGE_B + g * 16, lsrc + (ks + 2) * 64 + g * 16);
        }
        cp_commit();   // keep group count uniform
    }

    // ---- epilogue: per-row top-2 over this warp's 64 codes ----
    const int r0 = lane >> 2;
    const int cc = (lane & 3) * 2;
    #pragma unroll
    for (int mi = 0; mi < 2; mi++) {
        #pragma unroll
        for (int h = 0; h < 2; h++) {
            ull k1 = 0, k2 = 0;
            #pragma unroll
            for (int ni = 0; ni < 8; ni++) {
                #pragma unroll
                for (int c = 0; c < 2; c++) {
                    const int n = ntile * 128 + wn * 64 + ni * 8 + cc + c;
                    const float sc = acc[mi][ni][h * 2 + c] - __ldg(&g_hn[n]);
                    const ull key = ((ull)mono_f32(sc) << 32) | (ull)(NE - 1 - n);
                    if (key > k1) { k2 = k1; k1 = key; }
                    else if (key > k2) { k2 = key; }
                }
            }
            #pragma unroll
            for (int off = 1; off <= 2; off <<= 1) {
                ull o1 = __shfl_xor_sync(0xffffffffu, k1, off);
                ull o2 = __shfl_xor_sync(0xffffffffu, k2, off);
                ull n1 = umax64(k1, o1);
                ull n2 = umax64(umin64(k1, o1), umax64(k2, o2));
                k1 = n1; k2 = n2;
            }
            if ((lane & 3) == 0) {
                const int token = mtile * 128 + wm * 32 + mi * 16 + h * 8 + r0;
                ull* dst = g_top + (size_t)token * 512 + ntile * 4 + wn * 2;
                dst[0] = k1;
                dst[1] = k2;
            }
        }
    }
}

// ================= fixup: top-4 exact fp32 rescore =================
__global__ void fixup_kernel(const float* __restrict__ z, const float* __restrict__ cb) {
    const int token = blockIdx.x * 8 + (threadIdx.x >> 5);
    const int lane = threadIdx.x & 31;

    const ull* tp = g_top + (size_t)token * 512;
    ull k[16];
    #pragma unroll
    for (int i = 0; i < 16; i++) k[i] = tp[lane + 32 * i];

    int cand[4];
    #pragma unroll
    for (int r = 0; r < 4; r++) {
        ull m = 0;
        #pragma unroll
        for (int i = 0; i < 16; i++) m = umax64(m, k[i]);
        #pragma unroll
        for (int off = 16; off; off >>= 1)
            m = umax64(m, __shfl_xor_sync(0xffffffffu, m, off));
        #pragma unroll
        for (int i = 0; i < 16; i++) if (k[i] == m) k[i] = 0;
        cand[r] = (NE - 1) - (int)(m & 0xFFFFFFFFull);
    }

    const int bb = token >> 10, p = token & 1023;
    float zv[8];
    #pragma unroll
    for (int i = 0; i < 8; i++)
        zv[i] = z[((size_t)bb * CD + lane + 32 * i) * HW + p];

    ull bestk = 0;
    #pragma unroll
    for (int r = 0; r < 4; r++) {
        const int n = cand[r];
        const float* crow = cb + (size_t)n * CD;
        float s = 0.f;
        #pragma unroll
        for (int i = 0; i < 8; i++) s = fmaf(zv[i], __ldg(&crow[lane + 32 * i]), s);
        #pragma unroll
        for (int off = 16; off; off >>= 1) s += __shfl_xor_sync(0xffffffffu, s, off);
        s -= g_hn[n];
        const ull key = ((ull)mono_f32(s) << 32) | (ull)(NE - 1 - n);
        bestk = umax64(bestk, key);
    }
    if (lane == 0) g_best[token] = (NE - 1) - (int)(bestk & 0xFFFFFFFFull);
}

// ================= gather z_q =================
__global__ void gather_kernel(const float* __restrict__ cb, float* __restrict__ out) {
    const int tid = threadIdx.x;
    const int w = tid >> 5, l = tid & 31;
    const int token = blockIdx.x * 32 + l;
    const int n = g_best[token];
    const int bb = token >> 10, p = token & 1023;
    const float* crow = cb + (size_t)n * CD;
    float* ob = out + (size_t)bb * CD * HW + p;
    #pragma unroll 4
    for (int i = 0; i < 32; i++) {
        const int c = w + 8 * i;
        ob[(size_t)c * HW] = crow[c];
    }
}

// ================= spherical distance loss =================
__global__ void sph_kernel(const float* __restrict__ ie, const float* __restrict__ pr,
                           float* __restrict__ out) {
    int e = blockIdx.x * blockDim.x + threadIdx.x;
    if (e >= EMB) return;
    float p[BATCH];
    float pn = 0.f;
    #pragma unroll
    for (int b = 0; b < BATCH; b++) { p[b] = pr[b * EMB + e]; pn += p[b] * p[b]; }
    pn = fmaxf(sqrtf(pn), 1e-12f);
    #pragma unroll
    for (int b = 0; b < BATCH; b++) p[b] /= pn;
    float acc = 0.f;
    for (int j = 0; j < NCUTS; j++) {
        float q[BATCH];
        float qn = 0.f;
        #pragma unroll
        for (int b = 0; b < BATCH; b++) {
            q[b] = ie[(size_t)(j * BATCH + b) * EMB + e];
            qn += q[b] * q[b];
        }
        qn = fmaxf(sqrtf(qn), 1e-12f);
        float d2 = 0.f;
        #pragma unroll
        for (int b = 0; b < BATCH; b++) {
            float df = q[b] / qn - p[b];
            d2 += df * df;
        }
        float h = fminf(0.5f * sqrtf(d2), 1.0f);
        float a = asinf(h);
        acc += 2.0f * a * a;
    }
    out[e] = acc * (1.0f / NCUTS);
}

// ================= launch =================
extern "C" void kernel_launch(void* const* d_in, const int* in_sizes, int n_in,
                              void* d_out, int out_size) {
    const float* z  = (const float*)d_in[0];   // [4,256,32,32]
    const float* cb = (const float*)d_in[1];   // [16384,256]
    const float* ie = (const float*)d_in[2];   // [32,4,512]
    const float* pr = (const float*)d_in[3];   // [4,512]
    float* out = (float*)d_out;

    convA_kernel<<<(NTOK * 32) / 256, 256>>>(z);
    convB_kernel<<<(NE * 32) / 256, 256>>>(cb);
    halfnorm_kernel<<<NE / 8, 256>>>(cb);
    vq_gemm<<<dim3(128, 32), 256, SMEM_B>>>();
    fixup_kernel<<<NTOK / 8, 256>>>(z, cb);
    gather_kernel<<<NTOK / 32, 256>>>(cb, out);
    if (out_size >= ZQ_N + EMB)
        sph_kernel<<<(EMB + 255) / 256, 256>>>(ie, pr, out + ZQ_N);
}

// round 4
// speedup vs baseline: 5.8859x; 1.1916x over previous
#include <cuda_runtime.h>
#include <cuda_bf16.h>
#include <cstdint>
#include <math.h>

typedef unsigned long long ull;

// ---------------- problem dims ----------------
#define NE     16384
#define CD     256
#define HW     1024
#define NTOK   4096
#define ZQ_N   (NTOK * CD)
#define NCUTS  32
#define EMB    512
#define BATCH  4

// ---------------- GEMM tiling ----------------
// CTA: 128 tokens x 512 codes. A resident in smem; B streamed (4 ntiles x 4 kslices).
#define NTG     4                    // ntiles per CTA (128 codes each)
#define AROW    528                  // 512B data + 16B pad (conflict-free ldmatrix)
#define APLANE  (128 * AROW)         // 67584
#define BROW    144                  // 128B data + 16B pad
#define BTILE   (128 * BROW)         // 18432
#define SMEM_B  (APLANE + 2 * BTILE) // 104448

// ---------------- device globals ----------------
__device__ __align__(16) __nv_bfloat16 g_Ah[NTOK * CD];
__device__ __align__(16) __nv_bfloat16 g_Bh[NE * CD];
__device__ float g_hn[NE];
__device__ ull   g_top[(size_t)NTOK * 128];   // top-2 per (token, ngroup(32), wn(2))
__device__ int   g_best[NTOK];

// ---------------- asm helpers ----------------
static __device__ __forceinline__ uint32_t smem_u32(const void* p) {
    uint32_t a;
    asm("{ .reg .u64 t; cvta.to.shared.u64 t, %1; cvt.u32.u64 %0, t; }" : "=r"(a) : "l"(p));
    return a;
}
static __device__ __forceinline__ void cp16(uint32_t dst, const void* src) {
    asm volatile("cp.async.cg.shared.global [%0], [%1], 16;" :: "r"(dst), "l"(src));
}
static __device__ __forceinline__ void cp_commit() {
    asm volatile("cp.async.commit_group;");
}
template <int N> static __device__ __forceinline__ void cp_wait() {
    asm volatile("cp.async.wait_group %0;" :: "n"(N));
}
#define LDSM4(r, addr) \
    asm volatile("ldmatrix.sync.aligned.m8n8.x4.shared.b16 {%0,%1,%2,%3}, [%4];" \
        : "=r"((r)[0]), "=r"((r)[1]), "=r"((r)[2]), "=r"((r)[3]) : "r"(addr))
#define MMA16816(d, a, b0, b1) \
    asm volatile("mma.sync.aligned.m16n8k16.row.col.f32.bf16.bf16.f32 " \
        "{%0,%1,%2,%3},{%4,%5,%6,%7},{%8,%9},{%0,%1,%2,%3};" \
        : "+f"((d)[0]), "+f"((d)[1]), "+f"((d)[2]), "+f"((d)[3]) \
        : "r"((a)[0]), "r"((a)[1]), "r"((a)[2]), "r"((a)[3]), "r"(b0), "r"(b1))

static __device__ __forceinline__ uint32_t mono_f32(float f) {
    uint32_t b = __float_as_uint(f);
    return (b & 0x80000000u) ? ~b : (b | 0x80000000u);
}
static __device__ __forceinline__ ull umax64(ull a, ull b) { return a > b ? a : b; }
static __device__ __forceinline__ ull umin64(ull a, ull b) { return a < b ? a : b; }

// ================= prep: z -> bf16 token-major =================
__global__ void convA_kernel(const float* __restrict__ z) {
    int t = blockIdx.x * 256 + threadIdx.x;           // NTOK*32 threads
    int token = t >> 5, c8 = t & 31;
    int bb = token >> 10, p = token & 1023;
    __align__(16) __nv_bfloat16 h[8];
    #pragma unroll
    for (int i = 0; i < 8; i++)
        h[i] = __float2bfloat16(z[((size_t)bb * CD + c8 * 8 + i) * HW + p]);
    *(uint4*)&g_Ah[(size_t)token * CD + c8 * 8] = *(const uint4*)h;
}

// ================= prep: codebook -> bf16 + exact 0.5||e||^2 (fused) =================
__global__ void convBH_kernel(const float* __restrict__ cb) {
    int t = blockIdx.x * 256 + threadIdx.x;           // NE*32 threads, warp = one row
    int n = t >> 5, c8 = t & 31;
    __align__(16) __nv_bfloat16 h[8];
    float s = 0.f;
    #pragma unroll
    for (int i = 0; i < 8; i++) {
        float v = cb[(size_t)n * CD + c8 * 8 + i];
        h[i] = __float2bfloat16(v);
        s = fmaf(v, v, s);
    }
    *(uint4*)&g_Bh[(size_t)n * CD + c8 * 8] = *(const uint4*)h;
    #pragma unroll
    for (int o = 16; o; o >>= 1) s += __shfl_xor_sync(0xffffffffu, s, o);
    if ((t & 31) == 0) g_hn[n] = 0.5f * s;
}

// ================= tensor-core VQ GEMM (nomination pass) =================
__global__ void __launch_bounds__(256, 2) vq_gemm() {
    extern __shared__ unsigned char smem[];
    const uint32_t sb = smem_u32(smem);
    const int tid = threadIdx.x;
    const int lane = tid & 31;
    const int wid = tid >> 5;
    const int wm = wid >> 1, wn = wid & 1;   // 4 x 2 warp grid, warp tile 32x64
    const int ngrp  = blockIdx.x;            // 32 groups of 512 codes
    const int mtile = blockIdx.y;            // 32 tiles of 128 tokens

    const char* Abase = (const char*)(g_Ah + (size_t)mtile * 128 * CD);
    const char* Bbase = (const char*)(g_Bh + (size_t)ngrp * 512 * CD);

    // ---- prologue: resident A (128x256 bf16) + B slice 0 -> group0; B slice 1 -> group1
    {
        const int row = tid & 127, half = tid >> 7;
        const char* asrc = Abase + (size_t)row * 512 + half * 256;
        const uint32_t adst = sb + row * AROW + half * 256;
        #pragma unroll
        for (int j = 0; j < 16; j++)
            cp16(adst + j * 16, asrc + j * 16);
    }
    const int brow = tid >> 1, bg = (tid & 1) * 64;
    const uint32_t bdst0 = sb + APLANE + brow * BROW + bg;
    {
        const char* bsrc = Bbase + (size_t)brow * 512 + bg;        // nt=0, ks=0
        #pragma unroll
        for (int j = 0; j < 4; j++) cp16(bdst0 + j * 16, bsrc + j * 16);
        cp_commit();
        const char* bsrc1 = Bbase + (size_t)brow * 512 + 128 + bg; // nt=0, ks=1
        #pragma unroll
        for (int j = 0; j < 4; j++) cp16(bdst0 + BTILE + j * 16, bsrc1 + j * 16);
        cp_commit();
    }

    float acc[2][8][4];
    #pragma unroll
    for (int mi = 0; mi < 2; mi++)
        #pragma unroll
        for (int ni = 0; ni < 8; ni++)
            #pragma unroll
            for (int c = 0; c < 4; c++) acc[mi][ni][c] = 0.f;

    ull k1[2][2], k2[2][2];
    #pragma unroll
    for (int mi = 0; mi < 2; mi++)
        #pragma unroll
        for (int h = 0; h < 2; h++) { k1[mi][h] = 0; k2[mi][h] = 0; }

    const uint32_t a_addr = sb + (wm * 32 + (lane & 15)) * AROW + (lane >> 4) * 16;
    const uint32_t b_addr = sb + APLANE + (wn * 64 + (lane & 15)) * BROW + (lane >> 4) * 16;
    const int cc = (lane & 3) * 2;

    for (int siter = 0; siter < 4 * NTG; siter++) {
        const int s = siter & 1;
        const int nt = siter >> 2, ks = siter & 3;

        cp_wait<1>();
        __syncthreads();

        const uint32_t bb = b_addr + s * BTILE;
        const uint32_t aa = a_addr + ks * 128;
        #pragma unroll
        for (int kk = 0; kk < 4; kk++) {
            uint32_t a[2][4], b[4][4];
            #pragma unroll
            for (int mi = 0; mi < 2; mi++)
                LDSM4(a[mi], aa + mi * 16 * AROW + kk * 32);
            #pragma unroll
            for (int nf = 0; nf < 4; nf++)
                LDSM4(b[nf], bb + nf * 16 * BROW + kk * 32);
            #pragma unroll
            for (int mi = 0; mi < 2; mi++)
                #pragma unroll
                for (int nf = 0; nf < 4; nf++) {
                    MMA16816(acc[mi][nf * 2 + 0], a[mi], b[nf][0], b[nf][2]);
                    MMA16816(acc[mi][nf * 2 + 1], a[mi], b[nf][1], b[nf][3]);
                }
        }
        __syncthreads();

        // prefetch slice siter+2 into stage s
        const int nsi = siter + 2;
        if (nsi < 4 * NTG) {
            const int nnt = nsi >> 2, nks = nsi & 3;
            const char* bsrc = Bbase + (size_t)(nnt * 128 + brow) * 512 + nks * 128 + bg;
            #pragma unroll
            for (int j = 0; j < 4; j++) cp16(bdst0 + s * BTILE + j * 16, bsrc + j * 16);
        }
        cp_commit();

        // ntile boundary: fold acc into running top-2, reset acc
        if (ks == 3) {
            const int nbase = ngrp * 512 + nt * 128 + wn * 64;
            #pragma unroll
            for (int ni = 0; ni < 8; ni++) {
                #pragma unroll
                for (int c = 0; c < 2; c++) {
                    const int n = nbase + ni * 8 + cc + c;
                    const float hn = __ldg(&g_hn[n]);
                    const ull lowkey = (ull)(NE - 1 - n);
                    #pragma unroll
                    for (int mi = 0; mi < 2; mi++)
                        #pragma unroll
                        for (int h = 0; h < 2; h++) {
                            const float sc = acc[mi][ni][h * 2 + c] - hn;
                            const ull key = ((ull)mono_f32(sc) << 32) | lowkey;
                            if (key > k1[mi][h]) { k2[mi][h] = k1[mi][h]; k1[mi][h] = key; }
                            else if (key > k2[mi][h]) { k2[mi][h] = key; }
                            acc[mi][ni][h * 2 + c] = 0.f;
                        }
                }
            }
        }
    }

    // quad-reduce top-2 and publish (2 keys per token per wn)
    #pragma unroll
    for (int mi = 0; mi < 2; mi++)
        #pragma unroll
        for (int h = 0; h < 2; h++) {
            ull a1 = k1[mi][h], a2 = k2[mi][h];
            #pragma unroll
            for (int off = 1; off <= 2; off <<= 1) {
                ull o1 = __shfl_xor_sync(0xffffffffu, a1, off);
                ull o2 = __shfl_xor_sync(0xffffffffu, a2, off);
                ull n1 = umax64(a1, o1);
                ull n2 = umax64(umin64(a1, o1), umax64(a2, o2));
                a1 = n1; a2 = n2;
            }
            if ((lane & 3) == 0) {
                const int token = mtile * 128 + wm * 32 + mi * 16 + h * 8 + (lane >> 2);
                ull* dst = g_top + (size_t)token * 128 + ngrp * 4 + wn * 2;
                dst[0] = a1;
                dst[1] = a2;
            }
        }
}

// ================= fixup: global top-4 + exact fp32 rescore =================
__global__ void fixup_kernel(const float* __restrict__ z, const float* __restrict__ cb) {
    const int token = blockIdx.x * 8 + (threadIdx.x >> 5);
    const int lane = threadIdx.x & 31;

    const ull* tp = g_top + (size_t)token * 128;
    ull k[4];
    #pragma unroll
    for (int i = 0; i < 4; i++) k[i] = tp[lane + 32 * i];

    int cand[4];
    #pragma unroll
    for (int r = 0; r < 4; r++) {
        ull m = 0;
        #pragma unroll
        for (int i = 0; i < 4; i++) m = umax64(m, k[i]);
        #pragma unroll
        for (int off = 16; off; off >>= 1)
            m = umax64(m, __shfl_xor_sync(0xffffffffu, m, off));
        #pragma unroll
        for (int i = 0; i < 4; i++) if (k[i] == m) k[i] = 0;
        cand[r] = (NE - 1) - (int)(m & 0xFFFFFFFFull);
    }

    const int bb = token >> 10, p = token & 1023;
    float zv[8];
    #pragma unroll
    for (int i = 0; i < 8; i++)
        zv[i] = z[((size_t)bb * CD + lane + 32 * i) * HW + p];

    ull bestk = 0;
    #pragma unroll
    for (int r = 0; r < 4; r++) {
        const int n = cand[r];
        const float* crow = cb + (size_t)n * CD;
        float s = 0.f;
        #pragma unroll
        for (int i = 0; i < 8; i++) s = fmaf(zv[i], __ldg(&crow[lane + 32 * i]), s);
        #pragma unroll
        for (int off = 16; off; off >>= 1) s += __shfl_xor_sync(0xffffffffu, s, off);
        s -= g_hn[n];
        const ull key = ((ull)mono_f32(s) << 32) | (ull)(NE - 1 - n);
        bestk = umax64(bestk, key);
    }
    if (lane == 0) g_best[token] = (NE - 1) - (int)(bestk & 0xFFFFFFFFull);
}

// ================= gather z_q + spherical distance (fused) =================
__global__ void gather_sph_kernel(const float* __restrict__ cb, const float* __restrict__ ie,
                                  const float* __restrict__ pr, float* __restrict__ out) {
    if (blockIdx.x < NTOK / 32) {
        const int tid = threadIdx.x;
        const int w = tid >> 5, l = tid & 31;
        const int token = blockIdx.x * 32 + l;
        const int n = g_best[token];
        const int bb = token >> 10, p = token & 1023;
        const float* crow = cb + (size_t)n * CD;
        float* ob = out + (size_t)bb * CD * HW + p;
        #pragma unroll 4
        for (int i = 0; i < 32; i++) {
            const int c = w + 8 * i;
            ob[(size_t)c * HW] = crow[c];
        }
        return;
    }
    const int e = (blockIdx.x - NTOK / 32) * 256 + threadIdx.x;
    if (e >= EMB) return;
    float pv[BATCH];
    float pn = 0.f;
    #pragma unroll
    for (int b = 0; b < BATCH; b++) { pv[b] = pr[b * EMB + e]; pn += pv[b] * pv[b]; }
    pn = fmaxf(sqrtf(pn), 1e-12f);
    #pragma unroll
    for (int b = 0; b < BATCH; b++) pv[b] /= pn;
    float acc = 0.f;
    for (int j = 0; j < NCUTS; j++) {
        float q[BATCH];
        float qn = 0.f;
        #pragma unroll
        for (int b = 0; b < BATCH; b++) {
            q[b] = ie[(size_t)(j * BATCH + b) * EMB + e];
            qn += q[b] * q[b];
        }
        qn = fmaxf(sqrtf(qn), 1e-12f);
        float d2 = 0.f;
        #pragma unroll
        for (int b = 0; b < BATCH; b++) {
            float df = q[b] / qn - pv[b];
            d2 += df * df;
        }
        float h = fminf(0.5f * sqrtf(d2), 1.0f);
        float a = asinf(h);
        acc += 2.0f * a * a;
    }
    out[ZQ_N + e] = acc * (1.0f / NCUTS);
}

// ================= launch =================
extern "C" void kernel_launch(void* const* d_in, const int* in_sizes, int n_in,
                              void* d_out, int out_size) {
    const float* z  = (const float*)d_in[0];
    const float* cb = (const float*)d_in[1];
    const float* ie = (const float*)d_in[2];
    const float* pr = (const float*)d_in[3];
    float* out = (float*)d_out;

    cudaFuncSetAttribute(vq_gemm, cudaFuncAttributeMaxDynamicSharedMemorySize, SMEM_B);

    convA_kernel<<<(NTOK * 32) / 256, 256>>>(z);
    convBH_kernel<<<(NE * 32) / 256, 256>>>(cb);
    vq_gemm<<<dim3(NE / 512, NTOK / 128), 256, SMEM_B>>>();
    fixup_kernel<<<NTOK / 8, 256>>>(z, cb);
    gather_sph_kernel<<<NTOK / 32 + 2, 256>>>(cb, ie, pr, out);
}